// round 15
// baseline (speedup 1.0000x reference)
#include <cuda_runtime.h>
#include <cuda_bf16.h>
#include <math.h>
#include <stdint.h>

#define N_B 4
#define T_S 4096
#define DIN 1024
#define D_E 128
#define NT (N_B * T_S)
#define PCH 40      // smem row pitch in halfs (32 + 8 pad)
#define BUFSZ 40960 // one stage: 4 regions x 10240B

// ---- scratch (device globals: allocation-free) ----
__device__ __nv_bfloat16 g_wth[3 * D_E * DIN];
__device__ __nv_bfloat16 g_wtl[3 * D_E * DIN];
__device__ __nv_bfloat16 g_qh[NT * D_E];
__device__ __nv_bfloat16 g_ql[NT * D_E];
__device__ __nv_bfloat16 g_kh[NT * D_E];
__device__ __nv_bfloat16 g_kl[NT * D_E];
__device__ __nv_bfloat16 g_vth[(long)N_B * D_E * T_S];
__device__ __nv_bfloat16 g_vtl[(long)N_B * D_E * T_S];
__device__ float g_pmax[(long)NT * 32];
__device__ float g_psum[(long)NT * 32];
// split-K partials: [n][i-4][jg<8][128*128] for i in 4..31
__device__ float g_part[(long)4 * 28 * 8 * 128 * 128];
__device__ float g_out_fallback[NT * D_E];

__device__ __forceinline__ float neg_inf() { return __int_as_float(0xff800000); }

__device__ __forceinline__ uint32_t smem_u32(const void* p) {
    uint32_t a;
    asm("{ .reg .u64 t; cvta.to.shared.u64 t, %1; cvt.u32.u64 %0, t; }" : "=r"(a) : "l"(p));
    return a;
}
__device__ __forceinline__ void split_bf16(float x, __nv_bfloat16& h, __nv_bfloat16& l) {
    h = __float2bfloat16(x);
    l = __float2bfloat16(x - __bfloat162float(h));
}

#define CP16(dst, src) asm volatile("cp.async.cg.shared.global [%0], [%1], 16;" :: "r"(dst), "l"(src))
#define CPCOMMIT() asm volatile("cp.async.commit_group;" ::: "memory")
#define CPWAIT0() asm volatile("cp.async.wait_group 0;" ::: "memory")

__device__ __forceinline__ void ldsm_x4(uint32_t* r, uint32_t addr) {
    asm volatile("ldmatrix.sync.aligned.m8n8.x4.shared.b16 {%0,%1,%2,%3}, [%4];"
        : "=r"(r[0]), "=r"(r[1]), "=r"(r[2]), "=r"(r[3]) : "r"(addr));
}
__device__ __forceinline__ void mma_bf16(float* c, const uint32_t* a, const uint32_t* b) {
    asm volatile(
        "mma.sync.aligned.m16n8k16.row.col.f32.bf16.bf16.f32 "
        "{%0,%1,%2,%3}, {%4,%5,%6,%7}, {%8,%9}, {%0,%1,%2,%3};"
        : "+f"(c[0]), "+f"(c[1]), "+f"(c[2]), "+f"(c[3])
        : "r"(a[0]), "r"(a[1]), "r"(a[2]), "r"(a[3]), "r"(b[0]), "r"(b[1]));
}

// One k16 step, mt-serial. B frags loaded as nt-pair x4 (both k-halves).
// Region layout within a stage: Ah@0, Al@10240, Bh@20480, Bl@30720.
__device__ __forceinline__ void mma_tile_step2(uint32_t base, int ks,
                                               uint32_t aoff, uint32_t boff2,
                                               float (*acc)[4][4])
{
    uint32_t ko = (uint32_t)ks * 32;
    uint32_t bh[4][2], bl[4][2];
#pragma unroll
    for (int p = 0; p < 2; p++) {
        uint32_t r[4];
        uint32_t ro = boff2 + p * (16 * 80) + ko;
        ldsm_x4(r, base + 20480 + ro);
        bh[2 * p][0] = r[0]; bh[2 * p][1] = r[1];
        bh[2 * p + 1][0] = r[2]; bh[2 * p + 1][1] = r[3];
        ldsm_x4(r, base + 30720 + ro);
        bl[2 * p][0] = r[0]; bl[2 * p][1] = r[1];
        bl[2 * p + 1][0] = r[2]; bl[2 * p + 1][1] = r[3];
    }
#pragma unroll
    for (int mt = 0; mt < 4; mt++) {
        uint32_t ah[4], al[4];
        uint32_t ro = aoff + mt * (16 * 80) + ko;
        ldsm_x4(ah, base + ro);
        ldsm_x4(al, base + 10240 + ro);
#pragma unroll
        for (int nt = 0; nt < 4; nt++) {
            mma_bf16(acc[mt][nt], ah, bh[nt]);
            mma_bf16(acc[mt][nt], ah, bl[nt]);
            mma_bf16(acc[mt][nt], al, bh[nt]);
        }
    }
}

#define MK_AOFF(wm, lane) ((uint32_t)((wm) + ((lane) & 15)) * 80 + ((lane) >> 4) * 16)
#define MK_BOFF2(wn, lane) \
    ((uint32_t)((wn) + (((lane) >> 4) << 3) + ((lane) & 7)) * 80 + (((lane) >> 3) & 1) * 16)

// ============================================================
// K0: transpose + split W
// ============================================================
__global__ __launch_bounds__(256) void wt_kernel(const float* __restrict__ Wq,
                                                 const float* __restrict__ Wk,
                                                 const float* __restrict__ Wv)
{
    const float* W = (blockIdx.z == 0) ? Wq : ((blockIdx.z == 1) ? Wk : Wv);
    __shared__ float t[32][33];
    int tid = threadIdx.x;
    int tx = tid & 31, ty = tid >> 5;
    int k0 = blockIdx.x * 32, n0 = blockIdx.y * 32;
#pragma unroll
    for (int s = 0; s < 4; s++) t[ty + s * 8][tx] = W[(k0 + ty + s * 8) * D_E + n0 + tx];
    __syncthreads();
    long wb = (long)blockIdx.z * D_E * DIN;
#pragma unroll
    for (int s = 0; s < 4; s++) {
        int n = n0 + ty + s * 8, k = k0 + tx;
        __nv_bfloat16 h, l;
        split_bf16(t[tx][ty + s * 8], h, l);
        g_wth[wb + (long)n * DIN + k] = h;
        g_wtl[wb + (long)n * DIN + k] = l;
    }
}

// ============================================================
// K1: QKV. A = x fp32 via LDG + on-the-fly bf16 split.
// W via cp.async. grid (3, NT/128); 2 CTAs/SM.
// ============================================================
__global__ __launch_bounds__(256, 2) void qkv_mma_kernel(const float* __restrict__ x)
{
    extern __shared__ char smc[];
    uint32_t sb = smem_u32(smc);
    int tid = threadIdx.x, lane = tid & 31, wid = tid >> 5;
    int w = blockIdx.x;
    long mBase = (long)blockIdx.y * 128;

    const float* xA = x + mBase * DIN;
    const __nv_bfloat16* sBh = g_wth + (long)w * D_E * DIN;
    const __nv_bfloat16* sBl = g_wtl + (long)w * D_E * DIN;

    int n = (int)(mBase >> 12);

    int wm = (wid >> 2) * 64, wn = (wid & 3) * 32;
    uint32_t aoff = MK_AOFF(wm, lane);
    uint32_t boff2 = MK_BOFF2(wn, lane);

    float acc[4][4][4];
#pragma unroll
    for (int a = 0; a < 4; a++)
#pragma unroll
        for (int b = 0; b < 4; b++)
#pragma unroll
            for (int cc = 0; cc < 4; cc++) acc[a][b][cc] = 0.f;

    int arow = tid >> 3, aseg = tid & 7;

#define QKV_LDW(c, bf)                                                         \
    {                                                                          \
        int k0_ = (c) * 32;                                                    \
        uint32_t db_ = sb + (bf) * BUFSZ + 20480;                              \
        for (int u = tid; u < 1024; u += 256) {                                \
            int arr = u >> 9, idx = u & 511, row = idx >> 2, seg = idx & 3;    \
            const __nv_bfloat16* s = (arr ? sBl : sBh);                        \
            CP16(db_ + arr * 10240 + row * 80 + seg * 16,                      \
                 s + (long)row * DIN + k0_ + seg * 8);                         \
        }                                                                      \
        CPCOMMIT();                                                            \
    }

#define QKV_LDA(c, ar)                                                         \
    {                                                                          \
        int k0_ = (c) * 32;                                                    \
        _Pragma("unroll") for (int q = 0; q < 4; q++) {                        \
            ar[q] = *(const float4*)&xA[(long)(arow + q * 32) * DIN + k0_ + aseg * 4]; \
        }                                                                      \
    }

#define QKV_STA(bf, ar)                                                        \
    {                                                                          \
        _Pragma("unroll") for (int q = 0; q < 4; q++) {                        \
            __nv_bfloat16 h0, h1, h2, h3, l0, l1, l2, l3;                      \
            split_bf16(ar[q].x, h0, l0); split_bf16(ar[q].y, h1, l1);          \
            split_bf16(ar[q].z, h2, l2); split_bf16(ar[q].w, h3, l3);          \
            __nv_bfloat162 ph0, ph1, pl0, pl1;                                 \
            ph0.x = h0; ph0.y = h1; ph1.x = h2; ph1.y = h3;                    \
            pl0.x = l0; pl0.y = l1; pl1.x = l2; pl1.y = l3;                    \
            uint32_t so = (uint32_t)(arow + q * 32) * 80 + aseg * 8;           \
            *(uint2*)(smc + (bf) * BUFSZ + so) =                               \
                make_uint2(*(uint32_t*)&ph0, *(uint32_t*)&ph1);                \
            *(uint2*)(smc + (bf) * BUFSZ + 10240 + so) =                       \
                make_uint2(*(uint32_t*)&pl0, *(uint32_t*)&pl1);                \
        }                                                                      \
    }

    float4 ar[4];
    QKV_LDA(0, ar);
    QKV_LDW(0, 0);
    QKV_STA(0, ar);

    for (int c = 0; c < 32; c++) {
        CPWAIT0();
        __syncthreads();
        if (c + 1 < 32) {
            QKV_LDA(c + 1, ar);
            QKV_LDW(c + 1, (c + 1) & 1);
        }
        uint32_t base = sb + (c & 1) * BUFSZ;
        mma_tile_step2(base, 0, aoff, boff2, acc);
        mma_tile_step2(base, 1, aoff, boff2, acc);
        if (c + 1 < 32) QKV_STA((c + 1) & 1, ar);
    }
#undef QKV_LDW
#undef QKV_LDA
#undef QKV_STA
    __syncthreads();

    if (w < 2) {
        __nv_bfloat16* dh = w ? g_kh : g_qh;
        __nv_bfloat16* dl = w ? g_kl : g_ql;
#pragma unroll
        for (int mt = 0; mt < 4; mt++)
#pragma unroll
            for (int nt = 0; nt < 4; nt++) {
                int cc = wn + nt * 8 + (lane & 3) * 2;
#pragma unroll
                for (int h = 0; h < 2; h++) {
                    int row = wm + mt * 16 + (lane >> 2) + h * 8;
                    float v0 = acc[mt][nt][h * 2], v1 = acc[mt][nt][h * 2 + 1];
                    __nv_bfloat16 h0, h1, l0, l1;
                    split_bf16(v0, h0, l0);
                    split_bf16(v1, h1, l1);
                    __nv_bfloat162 ph, pl;
                    ph.x = h0; ph.y = h1; pl.x = l0; pl.y = l1;
                    long o = (mBase + row) * D_E + cc;
                    *(__nv_bfloat162*)&dh[o] = ph;
                    *(__nv_bfloat162*)&dl[o] = pl;
                }
            }
    } else {
        float* stage = (float*)smc;
#pragma unroll
        for (int mt = 0; mt < 4; mt++)
#pragma unroll
            for (int nt = 0; nt < 4; nt++) {
                int cc = wn + nt * 8 + (lane & 3) * 2;
#pragma unroll
                for (int h = 0; h < 2; h++) {
                    int row = wm + mt * 16 + (lane >> 2) + h * 8;
                    stage[row * 129 + cc] = acc[mt][nt][h * 2];
                    stage[row * 129 + cc + 1] = acc[mt][nt][h * 2 + 1];
                }
            }
        __syncthreads();
        int tb = (int)(mBase & (T_S - 1));
        for (int u = tid; u < 8192; u += 256) {
            int d = u >> 6, tp = (u & 63) * 2;
            float v0 = stage[tp * 129 + d];
            float v1 = stage[(tp + 1) * 129 + d];
            __nv_bfloat16 h0, h1, l0, l1;
            split_bf16(v0, h0, l0);
            split_bf16(v1, h1, l1);
            __nv_bfloat162 ph, pl;
            ph.x = h0; ph.y = h1; pl.x = l0; pl.y = l1;
            long o = ((long)n * D_E + d) * T_S + tb + tp;
            *(__nv_bfloat162*)&g_vth[o] = ph;
            *(__nv_bfloat162*)&g_vtl[o] = pl;
        }
    }
}

// ============================================================
// K2: scores. j>i tiles zero-fill; j<=i: S=QK^T, att stores
// u = exp(logit - M_tile), partials to g_pmax/g_psum.
// ============================================================
__global__ __launch_bounds__(256, 2) void scores_mma_kernel(float* __restrict__ att)
{
    int i = blockIdx.x >> 5;
    int j = blockIdx.x & 31;
    int n = blockIdx.y;
    float* attn = att + (long)n * T_S * T_S;

    int tid = threadIdx.x;

    if (j > i) {
        float4 z = make_float4(0.f, 0.f, 0.f, 0.f);
        float* tp = attn + (long)(i * 128) * T_S + j * 128;
#pragma unroll 4
        for (int u = tid; u < 4096; u += 256) {
            int row = u >> 5, c4 = u & 31;
            *(float4*)&tp[(long)row * T_S + c4 * 4] = z;
        }
        return;
    }

    extern __shared__ char smc[];
    uint32_t sb = smem_u32(smc);
    int lane = tid & 31, wid = tid >> 5;

    const __nv_bfloat16* sAh = g_qh + ((long)n * T_S + i * 128) * D_E;
    const __nv_bfloat16* sAl = g_ql + ((long)n * T_S + i * 128) * D_E;
    const __nv_bfloat16* sBh = g_kh + ((long)n * T_S + j * 128) * D_E;
    const __nv_bfloat16* sBl = g_kl + ((long)n * T_S + j * 128) * D_E;

    int wm = (wid >> 2) * 64, wn = (wid & 3) * 32;
    uint32_t aoff = MK_AOFF(wm, lane);
    uint32_t boff2 = MK_BOFF2(wn, lane);

    float acc[4][4][4];
#pragma unroll
    for (int a = 0; a < 4; a++)
#pragma unroll
        for (int b = 0; b < 4; b++)
#pragma unroll
            for (int cc = 0; cc < 4; cc++) acc[a][b][cc] = 0.f;

#define SC_LOAD(c, bf)                                                         \
    {                                                                          \
        int k0_ = (c) * 32;                                                    \
        uint32_t db_ = sb + (bf) * BUFSZ;                                      \
        for (int u = tid; u < 2048; u += 256) {                                \
            int arr = u >> 9, idx = u & 511, row = idx >> 2, seg = idx & 3;    \
            const __nv_bfloat16* s =                                           \
                (arr == 0) ? sAh : (arr == 1) ? sAl : (arr == 2) ? sBh : sBl;  \
            CP16(db_ + arr * 10240 + row * 80 + seg * 16,                      \
                 s + (long)row * D_E + k0_ + seg * 8);                         \
        }                                                                      \
        CPCOMMIT();                                                            \
    }

    SC_LOAD(0, 0);
    for (int c = 0; c < 4; c++) {
        CPWAIT0();
        __syncthreads();
        if (c + 1 < 4) SC_LOAD(c + 1, (c + 1) & 1);
        uint32_t base = sb + (c & 1) * BUFSZ;
        mma_tile_step2(base, 0, aoff, boff2, acc);
        mma_tile_step2(base, 1, aoff, boff2, acc);
    }
#undef SC_LOAD

    float* pm = (float*)(smc + 2 * BUFSZ);
    float* ps = pm + 512;
    float* sM = ps + 512;
    float NI = neg_inf();

    __syncthreads();
#pragma unroll
    for (int mt = 0; mt < 4; mt++)
#pragma unroll
        for (int h = 0; h < 2; h++) {
            int row = wm + mt * 16 + (lane >> 2) + h * 8;
            int tg = i * 128 + row;
            float m = NI;
#pragma unroll
            for (int nt = 0; nt < 4; nt++)
#pragma unroll
                for (int e = 0; e < 2; e++) {
                    int s = j * 128 + wn + nt * 8 + (lane & 3) * 2 + e;
                    if (s <= tg) {
                        float v = acc[mt][nt][h * 2 + e];
                        float ev = (v == 0.0f) ? NI : v;
                        m = fmaxf(m, ev);
                    }
                }
            m = fmaxf(m, __shfl_xor_sync(0xffffffffu, m, 1));
            m = fmaxf(m, __shfl_xor_sync(0xffffffffu, m, 2));
            if ((lane & 3) == 0) pm[row * 4 + (wid & 3)] = m;
        }
    __syncthreads();

    if (tid < 128) {
        float m0 = pm[tid * 4], m1 = pm[tid * 4 + 1], m2 = pm[tid * 4 + 2], m3 = pm[tid * 4 + 3];
        sM[tid] = fmaxf(fmaxf(m0, m1), fmaxf(m2, m3));
    }
    __syncthreads();

#pragma unroll
    for (int mt = 0; mt < 4; mt++)
#pragma unroll
        for (int h = 0; h < 2; h++) {
            int row = wm + mt * 16 + (lane >> 2) + h * 8;
            int tg = i * 128 + row;
            float M = sM[row];
            float ssum = 0.f;
            if (M != NI) {
#pragma unroll
                for (int nt = 0; nt < 4; nt++)
#pragma unroll
                    for (int e = 0; e < 2; e++) {
                        int s = j * 128 + wn + nt * 8 + (lane & 3) * 2 + e;
                        if (s <= tg) {
                            float v = acc[mt][nt][h * 2 + e];
                            float u = (v == 0.0f) ? 0.f : __expf(v - M);
                            attn[(long)tg * T_S + s] = u;
                            ssum += u;
                        }
                    }
            } else {
#pragma unroll
                for (int nt = 0; nt < 4; nt++)
#pragma unroll
                    for (int e = 0; e < 2; e++) {
                        int s = j * 128 + wn + nt * 8 + (lane & 3) * 2 + e;
                        if (s <= tg) attn[(long)tg * T_S + s] = 0.f;
                    }
            }
            ssum += __shfl_xor_sync(0xffffffffu, ssum, 1);
            ssum += __shfl_xor_sync(0xffffffffu, ssum, 2);
            if ((lane & 3) == 0) ps[row * 4 + (wid & 3)] = ssum;
        }
    __syncthreads();

    if (tid < 128) {
        float S = ps[tid * 4] + ps[tid * 4 + 1] + ps[tid * 4 + 2] + ps[tid * 4 + 3];
        long o = ((long)n * T_S + i * 128 + tid) * 32 + j;
        g_pmax[o] = sM[tid];
        g_psum[o] = S;
    }
}

// ============================================================
// K4: split-K PV, K-group = 512 cols (nc <= 16). grid (144, N_B).
// att holds u; p = u * f, f precomputed in smem.
// ============================================================
__global__ __launch_bounds__(256, 2) void pv_mma_kernel(float* __restrict__ att,
                                                        float* __restrict__ out)
{
    int b = blockIdx.x;
    int n = blockIdx.y;
    int i = 31, jg = 0;
    for (i = 31; i >= 0; --i) {
        int g = 1 + (i >> 2);
        if (b < g) { jg = b; break; }
        b -= g;
    }
    int ngroups = 1 + (i >> 2);
    int kStart = jg << 9;
    int kEndA = min((jg + 1) << 9, (i + 1) << 7);
    int nc = (kEndA - kStart) >> 5;

    extern __shared__ char smc[];
    uint32_t sb = smem_u32(smc);
    float* sf = (float*)(smc + 2 * BUFSZ);  // [128][32] = 16KB
    int tid = threadIdx.x, lane = tid & 31, wid = tid >> 5;

    float* attn = att + (long)n * T_S * T_S;

    if (tid < 128) {
        long r = (long)n * T_S + (i << 7) + tid;
        const float* pmr = g_pmax + r * 32;
        const float* psr = g_psum + r * 32;
        float NI = neg_inf();
        float M = NI;
        for (int jj = 0; jj <= i; jj++) M = fmaxf(M, pmr[jj]);
        float S = 0.f;
        for (int jj = 0; jj <= i; jj++) {
            float mj = pmr[jj];
            if (mj != NI) S += psr[jj] * __expf(mj - M);
        }
        float inv = 1.f / S;
        for (int jj = 0; jj <= i; jj++) {
            float mj = pmr[jj];
            sf[tid * 32 + jj] = (mj != NI) ? __expf(mj - M) * inv : 0.f;
        }
    }
    __syncthreads();

    int wm = (wid >> 2) * 64, wn = (wid & 3) * 32;
    uint32_t aoff = MK_AOFF(wm, lane);
    uint32_t boff2 = MK_BOFF2(wn, lane);

    float acc[4][4][4];
#pragma unroll
    for (int a = 0; a < 4; a++)
#pragma unroll
        for (int b2 = 0; b2 < 4; b2++)
#pragma unroll
            for (int cc = 0; cc < 4; cc++) acc[a][b2][cc] = 0.f;

#define PV_LDB(c, bf)                                                          \
    {                                                                          \
        int k0_ = kStart + (c) * 32;                                           \
        uint32_t db_ = sb + (bf) * BUFSZ + 20480;                              \
        for (int u = tid; u < 1024; u += 256) {                                \
            int arr = u >> 9, idx = u & 511, row = idx >> 2, seg = idx & 3;    \
            const __nv_bfloat16* s = (arr ? g_vtl : g_vth) +                   \
                ((long)n * D_E + row) * T_S + k0_ + seg * 8;                   \
            CP16(db_ + arr * 10240 + row * 80 + seg * 16, s);                  \
        }                                                                      \
        CPCOMMIT();                                                            \
    }

#define PV_LDA(c, ar)                                                          \
    {                                                                          \
        int k0_ = kStart + (c) * 32;                                           \
        _Pragma("unroll") for (int q = 0; q < 4; q++) {                        \
            int idx = tid + q * 256;                                           \
            int row = idx >> 3, seg = idx & 7;                                 \
            ar[q] = *(const float4*)&attn[(long)((i << 7) + row) * T_S + k0_ + seg * 4]; \
        }                                                                      \
    }

#define PV_PROC(c, ar, bf)                                                     \
    {                                                                          \
        int k0_ = kStart + (c) * 32;                                           \
        int jt_ = k0_ >> 7;                                                    \
        _Pragma("unroll") for (int q = 0; q < 4; q++) {                        \
            int idx = tid + q * 256;                                           \
            int row = idx >> 3, seg = idx & 7;                                 \
            int t = (i << 7) + row;                                            \
            int s0 = k0_ + seg * 4;                                            \
            float f = sf[row * 32 + jt_];                                      \
            float p0 = (s0 + 0 <= t) ? ar[q].x * f : 0.f;                      \
            float p1 = (s0 + 1 <= t) ? ar[q].y * f : 0.f;                      \
            float p2 = (s0 + 2 <= t) ? ar[q].z * f : 0.f;                      \
            float p3 = (s0 + 3 <= t) ? ar[q].w * f : 0.f;                      \
            *(float4*)&attn[(long)t * T_S + s0] = make_float4(p0, p1, p2, p3); \
            __nv_bfloat16 h0, h1, h2, h3, l0, l1, l2, l3;                      \
            split_bf16(p0, h0, l0); split_bf16(p1, h1, l1);                    \
            split_bf16(p2, h2, l2); split_bf16(p3, h3, l3);                    \
            __nv_bfloat162 ph0, ph1, pl0, pl1;                                 \
            ph0.x = h0; ph0.y = h1; ph1.x = h2; ph1.y = h3;                    \
            pl0.x = l0; pl0.y = l1; pl1.x = l2; pl1.y = l3;                    \
            uint32_t so = row * 80 + seg * 8;                                  \
            *(uint2*)(smc + (bf) * BUFSZ + so) =                               \
                make_uint2(*(uint32_t*)&ph0, *(uint32_t*)&ph1);                \
            *(uint2*)(smc + (bf) * BUFSZ + 10240 + so) =                       \
                make_uint2(*(uint32_t*)&pl0, *(uint32_t*)&pl1);                \
        }                                                                      \
    }

    float4 ar[4];
    PV_LDB(0, 0);
    PV_LDA(0, ar);
    PV_PROC(0, ar, 0);

    for (int c = 0; c < nc; c++) {
        CPWAIT0();
        __syncthreads();
        if (c + 1 < nc) {
            PV_LDB(c + 1, (c + 1) & 1);
            PV_LDA(c + 1, ar);
        }
        uint32_t base = sb + (c & 1) * BUFSZ;
        mma_tile_step2(base, 0, aoff, boff2, acc);
        mma_tile_step2(base, 1, aoff, boff2, acc);
        if (c + 1 < nc) PV_PROC(c + 1, ar, (c + 1) & 1);
    }
#undef PV_LDB
#undef PV_LDA
#undef PV_PROC

    float* dst;
    if (ngroups == 1) dst = out + ((long)n * T_S + (i << 7)) * D_E;
    else dst = g_part + (((long)(n * 28 + (i - 4)) * 8 + jg) << 14);
#pragma unroll
    for (int mt = 0; mt < 4; mt++)
#pragma unroll
        for (int nt = 0; nt < 4; nt++) {
            int cc = wn + nt * 8 + (lane & 3) * 2;
#pragma unroll
            for (int h = 0; h < 2; h++) {
                int row = wm + mt * 16 + (lane >> 2) + h * 8;
                *(float2*)&dst[(long)row * 128 + cc] =
                    make_float2(acc[mt][nt][h * 2], acc[mt][nt][h * 2 + 1]);
            }
        }
}

// ============================================================
// K5: reduce split-K partials. grid (112, N_B): 4 quarter-blocks
// per tile, tiles i = 4..31.
// ============================================================
__global__ void reduce_kernel(float* __restrict__ out)
{
    int ii = blockIdx.x >> 2;        // 0..27 -> i = ii + 4
    int quarter = blockIdx.x & 3;
    int n = blockIdx.y;
    int i = ii + 4;
    int ng = 1 + (i >> 2);
    const float* base = g_part + (((long)(n * 28 + ii) * 8) << 14) + quarter * 4096;
    float* o = out + ((long)n * T_S + (i << 7)) * D_E + quarter * 4096;
    for (int e = threadIdx.x * 4; e < 4096; e += 1024) {
        float4 s = *(const float4*)&base[e];
        for (int g = 1; g < ng; g++) {
            float4 p = *(const float4*)&base[((long)g << 14) + e];
            s.x += p.x; s.y += p.y; s.z += p.z; s.w += p.w;
        }
        *(float4*)&o[e] = s;
    }
}

// ============================================================
extern "C" void kernel_launch(void* const* d_in, const int* in_sizes, int n_in,
                              void* d_out, int out_size)
{
    const float* x  = (const float*)d_in[0];
    const float* Wq = (const float*)d_in[1];
    const float* Wk = (const float*)d_in[2];
    const float* Wv = (const float*)d_in[3];

    const long NTD = (long)NT * D_E;
    const long NTT = (long)N_B * T_S * T_S;

    float* dout = (float*)d_out;
    float* out_ptr;
    float* att_ptr;
    if ((long)out_size >= NTD + NTT) {
        out_ptr = dout;
        att_ptr = dout + NTD;
    } else if ((long)out_size == NTT) {
        att_ptr = dout;
        void* fb = nullptr;
        cudaGetSymbolAddress(&fb, g_out_fallback);
        out_ptr = (float*)fb;
    } else {
        out_ptr = dout;
        att_ptr = dout;
    }

    cudaFuncSetAttribute(qkv_mma_kernel, cudaFuncAttributeMaxDynamicSharedMemorySize, 2 * BUFSZ);
    cudaFuncSetAttribute(scores_mma_kernel, cudaFuncAttributeMaxDynamicSharedMemorySize, 2 * BUFSZ + 8192);
    cudaFuncSetAttribute(pv_mma_kernel, cudaFuncAttributeMaxDynamicSharedMemorySize, 2 * BUFSZ + 16384);

    wt_kernel<<<dim3(DIN / 32, D_E / 32, 3), 256>>>(Wq, Wk, Wv);

    qkv_mma_kernel<<<dim3(3, NT / 128), 256, 2 * BUFSZ>>>(x);

    scores_mma_kernel<<<dim3(1024, N_B), 256, 2 * BUFSZ + 8192>>>(att_ptr);

    pv_mma_kernel<<<dim3(144, N_B), 256, 2 * BUFSZ + 16384>>>(att_ptr, out_ptr);

    reduce_kernel<<<dim3(112, N_B), 256>>>(out_ptr);
}

// round 16
// speedup vs baseline: 1.0741x; 1.0741x over previous
#include <cuda_runtime.h>
#include <cuda_bf16.h>
#include <math.h>
#include <stdint.h>

#define N_B 4
#define T_S 4096
#define DIN 1024
#define D_E 128
#define NT (N_B * T_S)
#define PCH 40      // smem row pitch in halfs (32 + 8 pad)
#define BUFSZ 40960 // one stage: 4 regions x 10240B

// ---- scratch (device globals: allocation-free) ----
__device__ __nv_bfloat16 g_wth[3 * D_E * DIN];
__device__ __nv_bfloat16 g_wtl[3 * D_E * DIN];
__device__ __nv_bfloat16 g_qh[NT * D_E];
__device__ __nv_bfloat16 g_ql[NT * D_E];
__device__ __nv_bfloat16 g_kh[NT * D_E];
__device__ __nv_bfloat16 g_kl[NT * D_E];
__device__ __nv_bfloat16 g_vth[(long)N_B * D_E * T_S];
__device__ __nv_bfloat16 g_vtl[(long)N_B * D_E * T_S];
__device__ float g_pmax[(long)NT * 32];
__device__ float g_psum[(long)NT * 32];
// split-K partials: [n][i-8][jg<4][128*128] for i in 8..31
__device__ float g_part[(long)4 * 24 * 4 * 128 * 128];
__device__ float g_out_fallback[NT * D_E];

__device__ __forceinline__ float neg_inf() { return __int_as_float(0xff800000); }

__device__ __forceinline__ uint32_t smem_u32(const void* p) {
    uint32_t a;
    asm("{ .reg .u64 t; cvta.to.shared.u64 t, %1; cvt.u32.u64 %0, t; }" : "=r"(a) : "l"(p));
    return a;
}
__device__ __forceinline__ void split_bf16(float x, __nv_bfloat16& h, __nv_bfloat16& l) {
    h = __float2bfloat16(x);
    l = __float2bfloat16(x - __bfloat162float(h));
}

#define CP16(dst, src) asm volatile("cp.async.cg.shared.global [%0], [%1], 16;" :: "r"(dst), "l"(src))
#define CPCOMMIT() asm volatile("cp.async.commit_group;" ::: "memory")
#define CPWAIT0() asm volatile("cp.async.wait_group 0;" ::: "memory")

__device__ __forceinline__ void ldsm_x4(uint32_t* r, uint32_t addr) {
    asm volatile("ldmatrix.sync.aligned.m8n8.x4.shared.b16 {%0,%1,%2,%3}, [%4];"
        : "=r"(r[0]), "=r"(r[1]), "=r"(r[2]), "=r"(r[3]) : "r"(addr));
}
__device__ __forceinline__ void mma_bf16(float* c, const uint32_t* a, const uint32_t* b) {
    asm volatile(
        "mma.sync.aligned.m16n8k16.row.col.f32.bf16.bf16.f32 "
        "{%0,%1,%2,%3}, {%4,%5,%6,%7}, {%8,%9}, {%0,%1,%2,%3};"
        : "+f"(c[0]), "+f"(c[1]), "+f"(c[2]), "+f"(c[3])
        : "r"(a[0]), "r"(a[1]), "r"(a[2]), "r"(a[3]), "r"(b[0]), "r"(b[1]));
}

// One k16 step, mt-serial. B frags loaded as nt-pair x4 (both k-halves).
// Region layout within a stage: Ah@0, Al@10240, Bh@20480, Bl@30720.
__device__ __forceinline__ void mma_tile_step2(uint32_t base, int ks,
                                               uint32_t aoff, uint32_t boff2,
                                               float (*acc)[4][4])
{
    uint32_t ko = (uint32_t)ks * 32;
    uint32_t bh[4][2], bl[4][2];
#pragma unroll
    for (int p = 0; p < 2; p++) {
        uint32_t r[4];
        uint32_t ro = boff2 + p * (16 * 80) + ko;
        ldsm_x4(r, base + 20480 + ro);
        bh[2 * p][0] = r[0]; bh[2 * p][1] = r[1];
        bh[2 * p + 1][0] = r[2]; bh[2 * p + 1][1] = r[3];
        ldsm_x4(r, base + 30720 + ro);
        bl[2 * p][0] = r[0]; bl[2 * p][1] = r[1];
        bl[2 * p + 1][0] = r[2]; bl[2 * p + 1][1] = r[3];
    }
#pragma unroll
    for (int mt = 0; mt < 4; mt++) {
        uint32_t ah[4], al[4];
        uint32_t ro = aoff + mt * (16 * 80) + ko;
        ldsm_x4(ah, base + ro);
        ldsm_x4(al, base + 10240 + ro);
#pragma unroll
        for (int nt = 0; nt < 4; nt++) {
            mma_bf16(acc[mt][nt], ah, bh[nt]);
            mma_bf16(acc[mt][nt], ah, bl[nt]);
            mma_bf16(acc[mt][nt], al, bh[nt]);
        }
    }
}

#define MK_AOFF(wm, lane) ((uint32_t)((wm) + ((lane) & 15)) * 80 + ((lane) >> 4) * 16)
#define MK_BOFF2(wn, lane) \
    ((uint32_t)((wn) + (((lane) >> 4) << 3) + ((lane) & 7)) * 80 + (((lane) >> 3) & 1) * 16)

// ============================================================
// K0: transpose + split W
// ============================================================
__global__ __launch_bounds__(256) void wt_kernel(const float* __restrict__ Wq,
                                                 const float* __restrict__ Wk,
                                                 const float* __restrict__ Wv)
{
    const float* W = (blockIdx.z == 0) ? Wq : ((blockIdx.z == 1) ? Wk : Wv);
    __shared__ float t[32][33];
    int tid = threadIdx.x;
    int tx = tid & 31, ty = tid >> 5;
    int k0 = blockIdx.x * 32, n0 = blockIdx.y * 32;
#pragma unroll
    for (int s = 0; s < 4; s++) t[ty + s * 8][tx] = W[(k0 + ty + s * 8) * D_E + n0 + tx];
    __syncthreads();
    long wb = (long)blockIdx.z * D_E * DIN;
#pragma unroll
    for (int s = 0; s < 4; s++) {
        int n = n0 + ty + s * 8, k = k0 + tx;
        __nv_bfloat16 h, l;
        split_bf16(t[tx][ty + s * 8], h, l);
        g_wth[wb + (long)n * DIN + k] = h;
        g_wtl[wb + (long)n * DIN + k] = l;
    }
}

// ============================================================
// K1: QKV. A = x fp32 via LDG + on-the-fly bf16 split.
// W via cp.async. grid (3, NT/128); 2 CTAs/SM.
// ============================================================
__global__ __launch_bounds__(256, 2) void qkv_mma_kernel(const float* __restrict__ x)
{
    extern __shared__ char smc[];
    uint32_t sb = smem_u32(smc);
    int tid = threadIdx.x, lane = tid & 31, wid = tid >> 5;
    int w = blockIdx.x;
    long mBase = (long)blockIdx.y * 128;

    const float* xA = x + mBase * DIN;
    const __nv_bfloat16* sBh = g_wth + (long)w * D_E * DIN;
    const __nv_bfloat16* sBl = g_wtl + (long)w * D_E * DIN;

    int n = (int)(mBase >> 12);

    int wm = (wid >> 2) * 64, wn = (wid & 3) * 32;
    uint32_t aoff = MK_AOFF(wm, lane);
    uint32_t boff2 = MK_BOFF2(wn, lane);

    float acc[4][4][4];
#pragma unroll
    for (int a = 0; a < 4; a++)
#pragma unroll
        for (int b = 0; b < 4; b++)
#pragma unroll
            for (int cc = 0; cc < 4; cc++) acc[a][b][cc] = 0.f;

    int arow = tid >> 3, aseg = tid & 7;

#define QKV_LDW(c, bf)                                                         \
    {                                                                          \
        int k0_ = (c) * 32;                                                    \
        uint32_t db_ = sb + (bf) * BUFSZ + 20480;                              \
        for (int u = tid; u < 1024; u += 256) {                                \
            int arr = u >> 9, idx = u & 511, row = idx >> 2, seg = idx & 3;    \
            const __nv_bfloat16* s = (arr ? sBl : sBh);                        \
            CP16(db_ + arr * 10240 + row * 80 + seg * 16,                      \
                 s + (long)row * DIN + k0_ + seg * 8);                         \
        }                                                                      \
        CPCOMMIT();                                                            \
    }

#define QKV_LDA(c, ar)                                                         \
    {                                                                          \
        int k0_ = (c) * 32;                                                    \
        _Pragma("unroll") for (int q = 0; q < 4; q++) {                        \
            ar[q] = *(const float4*)&xA[(long)(arow + q * 32) * DIN + k0_ + aseg * 4]; \
        }                                                                      \
    }

#define QKV_STA(bf, ar)                                                        \
    {                                                                          \
        _Pragma("unroll") for (int q = 0; q < 4; q++) {                        \
            __nv_bfloat16 h0, h1, h2, h3, l0, l1, l2, l3;                      \
            split_bf16(ar[q].x, h0, l0); split_bf16(ar[q].y, h1, l1);          \
            split_bf16(ar[q].z, h2, l2); split_bf16(ar[q].w, h3, l3);          \
            __nv_bfloat162 ph0, ph1, pl0, pl1;                                 \
            ph0.x = h0; ph0.y = h1; ph1.x = h2; ph1.y = h3;                    \
            pl0.x = l0; pl0.y = l1; pl1.x = l2; pl1.y = l3;                    \
            uint32_t so = (uint32_t)(arow + q * 32) * 80 + aseg * 8;           \
            *(uint2*)(smc + (bf) * BUFSZ + so) =                               \
                make_uint2(*(uint32_t*)&ph0, *(uint32_t*)&ph1);                \
            *(uint2*)(smc + (bf) * BUFSZ + 10240 + so) =                       \
                make_uint2(*(uint32_t*)&pl0, *(uint32_t*)&pl1);                \
        }                                                                      \
    }

    float4 ar[4];
    QKV_LDA(0, ar);
    QKV_LDW(0, 0);
    QKV_STA(0, ar);

    for (int c = 0; c < 32; c++) {
        CPWAIT0();
        __syncthreads();
        if (c + 1 < 32) {
            QKV_LDA(c + 1, ar);
            QKV_LDW(c + 1, (c + 1) & 1);
        }
        uint32_t base = sb + (c & 1) * BUFSZ;
        mma_tile_step2(base, 0, aoff, boff2, acc);
        mma_tile_step2(base, 1, aoff, boff2, acc);
        if (c + 1 < 32) QKV_STA((c + 1) & 1, ar);
    }
#undef QKV_LDW
#undef QKV_LDA
#undef QKV_STA
    __syncthreads();

    if (w < 2) {
        __nv_bfloat16* dh = w ? g_kh : g_qh;
        __nv_bfloat16* dl = w ? g_kl : g_ql;
#pragma unroll
        for (int mt = 0; mt < 4; mt++)
#pragma unroll
            for (int nt = 0; nt < 4; nt++) {
                int cc = wn + nt * 8 + (lane & 3) * 2;
#pragma unroll
                for (int h = 0; h < 2; h++) {
                    int row = wm + mt * 16 + (lane >> 2) + h * 8;
                    float v0 = acc[mt][nt][h * 2], v1 = acc[mt][nt][h * 2 + 1];
                    __nv_bfloat16 h0, h1, l0, l1;
                    split_bf16(v0, h0, l0);
                    split_bf16(v1, h1, l1);
                    __nv_bfloat162 ph, pl;
                    ph.x = h0; ph.y = h1; pl.x = l0; pl.y = l1;
                    long o = (mBase + row) * D_E + cc;
                    *(__nv_bfloat162*)&dh[o] = ph;
                    *(__nv_bfloat162*)&dl[o] = pl;
                }
            }
    } else {
        float* stage = (float*)smc;
#pragma unroll
        for (int mt = 0; mt < 4; mt++)
#pragma unroll
            for (int nt = 0; nt < 4; nt++) {
                int cc = wn + nt * 8 + (lane & 3) * 2;
#pragma unroll
                for (int h = 0; h < 2; h++) {
                    int row = wm + mt * 16 + (lane >> 2) + h * 8;
                    stage[row * 129 + cc] = acc[mt][nt][h * 2];
                    stage[row * 129 + cc + 1] = acc[mt][nt][h * 2 + 1];
                }
            }
        __syncthreads();
        int tb = (int)(mBase & (T_S - 1));
        for (int u = tid; u < 8192; u += 256) {
            int d = u >> 6, tp = (u & 63) * 2;
            float v0 = stage[tp * 129 + d];
            float v1 = stage[(tp + 1) * 129 + d];
            __nv_bfloat16 h0, h1, l0, l1;
            split_bf16(v0, h0, l0);
            split_bf16(v1, h1, l1);
            __nv_bfloat162 ph, pl;
            ph.x = h0; ph.y = h1; pl.x = l0; pl.y = l1;
            long o = ((long)n * D_E + d) * T_S + tb + tp;
            *(__nv_bfloat162*)&g_vth[o] = ph;
            *(__nv_bfloat162*)&g_vtl[o] = pl;
        }
    }
}

// ============================================================
// K2: scores. j>i tiles zero-fill; j<=i: S=QK^T, att stores
// u = exp(logit - M_tile), staged in smem -> coalesced float4 writes.
// ============================================================
__global__ __launch_bounds__(256, 2) void scores_mma_kernel(float* __restrict__ att)
{
    int i = blockIdx.x >> 5;
    int j = blockIdx.x & 31;
    int n = blockIdx.y;
    float* attn = att + (long)n * T_S * T_S;

    int tid = threadIdx.x;

    if (j > i) {
        float4 z = make_float4(0.f, 0.f, 0.f, 0.f);
        float* tp = attn + (long)(i * 128) * T_S + j * 128;
#pragma unroll 4
        for (int u = tid; u < 4096; u += 256) {
            int row = u >> 5, c4 = u & 31;
            *(float4*)&tp[(long)row * T_S + c4 * 4] = z;
        }
        return;
    }

    extern __shared__ char smc[];
    uint32_t sb = smem_u32(smc);
    int lane = tid & 31, wid = tid >> 5;

    const __nv_bfloat16* sAh = g_qh + ((long)n * T_S + i * 128) * D_E;
    const __nv_bfloat16* sAl = g_ql + ((long)n * T_S + i * 128) * D_E;
    const __nv_bfloat16* sBh = g_kh + ((long)n * T_S + j * 128) * D_E;
    const __nv_bfloat16* sBl = g_kl + ((long)n * T_S + j * 128) * D_E;

    int wm = (wid >> 2) * 64, wn = (wid & 3) * 32;
    uint32_t aoff = MK_AOFF(wm, lane);
    uint32_t boff2 = MK_BOFF2(wn, lane);

    float acc[4][4][4];
#pragma unroll
    for (int a = 0; a < 4; a++)
#pragma unroll
        for (int b = 0; b < 4; b++)
#pragma unroll
            for (int cc = 0; cc < 4; cc++) acc[a][b][cc] = 0.f;

#define SC_LOAD(c, bf)                                                         \
    {                                                                          \
        int k0_ = (c) * 32;                                                    \
        uint32_t db_ = sb + (bf) * BUFSZ;                                      \
        for (int u = tid; u < 2048; u += 256) {                                \
            int arr = u >> 9, idx = u & 511, row = idx >> 2, seg = idx & 3;    \
            const __nv_bfloat16* s =                                           \
                (arr == 0) ? sAh : (arr == 1) ? sAl : (arr == 2) ? sBh : sBl;  \
            CP16(db_ + arr * 10240 + row * 80 + seg * 16,                      \
                 s + (long)row * D_E + k0_ + seg * 8);                         \
        }                                                                      \
        CPCOMMIT();                                                            \
    }

    SC_LOAD(0, 0);
    for (int c = 0; c < 4; c++) {
        CPWAIT0();
        __syncthreads();
        if (c + 1 < 4) SC_LOAD(c + 1, (c + 1) & 1);
        uint32_t base = sb + (c & 1) * BUFSZ;
        mma_tile_step2(base, 0, aoff, boff2, acc);
        mma_tile_step2(base, 1, aoff, boff2, acc);
    }
#undef SC_LOAD

    float* pm = (float*)(smc + 2 * BUFSZ);
    float* ps = pm + 512;
    float* sM = ps + 512;
    float* stage = (float*)smc;             // reuse ring buffers: [128][132]
    float NI = neg_inf();

    __syncthreads();
    // phase 1: per-warp (32-col group) maxes
#pragma unroll
    for (int mt = 0; mt < 4; mt++)
#pragma unroll
        for (int h = 0; h < 2; h++) {
            int row = wm + mt * 16 + (lane >> 2) + h * 8;
            int tg = i * 128 + row;
            float m = NI;
#pragma unroll
            for (int nt = 0; nt < 4; nt++)
#pragma unroll
                for (int e = 0; e < 2; e++) {
                    int s = j * 128 + wn + nt * 8 + (lane & 3) * 2 + e;
                    if (s <= tg) {
                        float v = acc[mt][nt][h * 2 + e];
                        float ev = (v == 0.0f) ? NI : v;
                        m = fmaxf(m, ev);
                    }
                }
            m = fmaxf(m, __shfl_xor_sync(0xffffffffu, m, 1));
            m = fmaxf(m, __shfl_xor_sync(0xffffffffu, m, 2));
            if ((lane & 3) == 0) pm[row * 4 + (wid & 3)] = m;
        }
    __syncthreads();

    // phase 2: tile max per row
    if (tid < 128) {
        float m0 = pm[tid * 4], m1 = pm[tid * 4 + 1], m2 = pm[tid * 4 + 2], m3 = pm[tid * 4 + 3];
        sM[tid] = fmaxf(fmaxf(m0, m1), fmaxf(m2, m3));
    }
    __syncthreads();

    // phase 3: u = exp(v - M_tile) into stage smem + per-group sums
#pragma unroll
    for (int mt = 0; mt < 4; mt++)
#pragma unroll
        for (int h = 0; h < 2; h++) {
            int row = wm + mt * 16 + (lane >> 2) + h * 8;
            int tg = i * 128 + row;
            float M = sM[row];
            float ssum = 0.f;
#pragma unroll
            for (int nt = 0; nt < 4; nt++)
#pragma unroll
                for (int e = 0; e < 2; e++) {
                    int col = wn + nt * 8 + (lane & 3) * 2 + e;
                    int s = j * 128 + col;
                    float u = 0.f;
                    if (s <= tg && M != NI) {
                        float v = acc[mt][nt][h * 2 + e];
                        if (v != 0.0f) {
                            u = __expf(v - M);
                            ssum += u;
                        }
                    }
                    stage[row * 132 + col] = u;
                }
            ssum += __shfl_xor_sync(0xffffffffu, ssum, 1);
            ssum += __shfl_xor_sync(0xffffffffu, ssum, 2);
            if ((lane & 3) == 0) ps[row * 4 + (wid & 3)] = ssum;
        }
    __syncthreads();

    // coalesced tile write: 512B per warp-row
    {
        float* tp = attn + (long)(i * 128) * T_S + j * 128;
#pragma unroll 4
        for (int u = tid; u < 4096; u += 256) {
            int row = u >> 5, c4 = u & 31;
            *(float4*)&tp[(long)row * T_S + c4 * 4] = *(float4*)&stage[row * 132 + c4 * 4];
        }
    }

    if (tid < 128) {
        float S = ps[tid * 4] + ps[tid * 4 + 1] + ps[tid * 4 + 2] + ps[tid * 4 + 3];
        long o = ((long)n * T_S + i * 128 + tid) * 32 + j;
        g_pmax[o] = sM[tid];
        g_psum[o] = S;
    }
}

// ============================================================
// K4: split-K PV, K-group = 1024 cols. grid (80, N_B).
// att holds u; p = u * f, f precomputed in smem.
// ============================================================
__global__ __launch_bounds__(256, 2) void pv_mma_kernel(float* __restrict__ att,
                                                        float* __restrict__ out)
{
    int b = blockIdx.x;
    int n = blockIdx.y;
    int i = 31, jg = 0;
    for (i = 31; i >= 0; --i) {
        int g = (i + 8) >> 3;
        if (b < g) { jg = b; break; }
        b -= g;
    }
    int ngroups = (i + 8) >> 3;
    int kStart = jg << 10;
    int kEndA = min((jg + 1) << 10, (i + 1) << 7);
    int nc = (kEndA - kStart) >> 5;

    extern __shared__ char smc[];
    uint32_t sb = smem_u32(smc);
    float* sf = (float*)(smc + 2 * BUFSZ);  // [128][32] = 16KB
    int tid = threadIdx.x, lane = tid & 31, wid = tid >> 5;

    float* attn = att + (long)n * T_S * T_S;

    if (tid < 128) {
        long r = (long)n * T_S + (i << 7) + tid;
        const float* pmr = g_pmax + r * 32;
        const float* psr = g_psum + r * 32;
        float NI = neg_inf();
        float M = NI;
        for (int jj = 0; jj <= i; jj++) M = fmaxf(M, pmr[jj]);
        float S = 0.f;
        for (int jj = 0; jj <= i; jj++) {
            float mj = pmr[jj];
            if (mj != NI) S += psr[jj] * __expf(mj - M);
        }
        float inv = 1.f / S;
        for (int jj = 0; jj <= i; jj++) {
            float mj = pmr[jj];
            sf[tid * 32 + jj] = (mj != NI) ? __expf(mj - M) * inv : 0.f;
        }
    }
    __syncthreads();

    int wm = (wid >> 2) * 64, wn = (wid & 3) * 32;
    uint32_t aoff = MK_AOFF(wm, lane);
    uint32_t boff2 = MK_BOFF2(wn, lane);

    float acc[4][4][4];
#pragma unroll
    for (int a = 0; a < 4; a++)
#pragma unroll
        for (int b2 = 0; b2 < 4; b2++)
#pragma unroll
            for (int cc = 0; cc < 4; cc++) acc[a][b2][cc] = 0.f;

#define PV_LDB(c, bf)                                                          \
    {                                                                          \
        int k0_ = kStart + (c) * 32;                                           \
        uint32_t db_ = sb + (bf) * BUFSZ + 20480;                              \
        for (int u = tid; u < 1024; u += 256) {                                \
            int arr = u >> 9, idx = u & 511, row = idx >> 2, seg = idx & 3;    \
            const __nv_bfloat16* s = (arr ? g_vtl : g_vth) +                   \
                ((long)n * D_E + row) * T_S + k0_ + seg * 8;                   \
            CP16(db_ + arr * 10240 + row * 80 + seg * 16, s);                  \
        }                                                                      \
        CPCOMMIT();                                                            \
    }

#define PV_LDA(c, ar)                                                          \
    {                                                                          \
        int k0_ = kStart + (c) * 32;                                           \
        _Pragma("unroll") for (int q = 0; q < 4; q++) {                        \
            int idx = tid + q * 256;                                           \
            int row = idx >> 3, seg = idx & 7;                                 \
            ar[q] = *(const float4*)&attn[(long)((i << 7) + row) * T_S + k0_ + seg * 4]; \
        }                                                                      \
    }

#define PV_PROC(c, ar, bf)                                                     \
    {                                                                          \
        int k0_ = kStart + (c) * 32;                                           \
        int jt_ = k0_ >> 7;                                                    \
        _Pragma("unroll") for (int q = 0; q < 4; q++) {                        \
            int idx = tid + q * 256;                                           \
            int row = idx >> 3, seg = idx & 7;                                 \
            int t = (i << 7) + row;                                            \
            int s0 = k0_ + seg * 4;                                            \
            float f = sf[row * 32 + jt_];                                      \
            float p0 = (s0 + 0 <= t) ? ar[q].x * f : 0.f;                      \
            float p1 = (s0 + 1 <= t) ? ar[q].y * f : 0.f;                      \
            float p2 = (s0 + 2 <= t) ? ar[q].z * f : 0.f;                      \
            float p3 = (s0 + 3 <= t) ? ar[q].w * f : 0.f;                      \
            *(float4*)&attn[(long)t * T_S + s0] = make_float4(p0, p1, p2, p3); \
            __nv_bfloat16 h0, h1, h2, h3, l0, l1, l2, l3;                      \
            split_bf16(p0, h0, l0); split_bf16(p1, h1, l1);                    \
            split_bf16(p2, h2, l2); split_bf16(p3, h3, l3);                    \
            __nv_bfloat162 ph0, ph1, pl0, pl1;                                 \
            ph0.x = h0; ph0.y = h1; ph1.x = h2; ph1.y = h3;                    \
            pl0.x = l0; pl0.y = l1; pl1.x = l2; pl1.y = l3;                    \
            uint32_t so = row * 80 + seg * 8;                                  \
            *(uint2*)(smc + (bf) * BUFSZ + so) =                               \
                make_uint2(*(uint32_t*)&ph0, *(uint32_t*)&ph1);                \
            *(uint2*)(smc + (bf) * BUFSZ + 10240 + so) =                       \
                make_uint2(*(uint32_t*)&pl0, *(uint32_t*)&pl1);                \
        }                                                                      \
    }

    float4 ar[4];
    PV_LDB(0, 0);
    PV_LDA(0, ar);
    PV_PROC(0, ar, 0);

    for (int c = 0; c < nc; c++) {
        CPWAIT0();
        __syncthreads();
        if (c + 1 < nc) {
            PV_LDB(c + 1, (c + 1) & 1);
            PV_LDA(c + 1, ar);
        }
        uint32_t base = sb + (c & 1) * BUFSZ;
        mma_tile_step2(base, 0, aoff, boff2, acc);
        mma_tile_step2(base, 1, aoff, boff2, acc);
        if (c + 1 < nc) PV_PROC(c + 1, ar, (c + 1) & 1);
    }
#undef PV_LDB
#undef PV_LDA
#undef PV_PROC

    float* dst;
    if (ngroups == 1) dst = out + ((long)n * T_S + (i << 7)) * D_E;
    else dst = g_part + (((long)(n * 24 + (i - 8)) * 4 + jg) << 14);
#pragma unroll
    for (int mt = 0; mt < 4; mt++)
#pragma unroll
        for (int nt = 0; nt < 4; nt++) {
            int cc = wn + nt * 8 + (lane & 3) * 2;
#pragma unroll
            for (int h = 0; h < 2; h++) {
                int row = wm + mt * 16 + (lane >> 2) + h * 8;
                *(float2*)&dst[(long)row * 128 + cc] =
                    make_float2(acc[mt][nt][h * 2], acc[mt][nt][h * 2 + 1]);
            }
        }
}

// ============================================================
// K5: reduce split-K partials. grid (96, N_B): 4 quarter-blocks
// per tile, tiles i = 8..31.
// ============================================================
__global__ void reduce_kernel(float* __restrict__ out)
{
    int ii = blockIdx.x >> 2;
    int quarter = blockIdx.x & 3;
    int n = blockIdx.y;
    int i = ii + 8;
    int ng = (i + 8) >> 3;
    const float* base = g_part + (((long)(n * 24 + ii) * 4) << 14) + quarter * 4096;
    float* o = out + ((long)n * T_S + (i << 7)) * D_E + quarter * 4096;
    for (int e = threadIdx.x * 4; e < 4096; e += 1024) {
        float4 s = *(const float4*)&base[e];
        for (int g = 1; g < ng; g++) {
            float4 p = *(const float4*)&base[((long)g << 14) + e];
            s.x += p.x; s.y += p.y; s.z += p.z; s.w += p.w;
        }
        *(float4*)&o[e] = s;
    }
}

// ============================================================
extern "C" void kernel_launch(void* const* d_in, const int* in_sizes, int n_in,
                              void* d_out, int out_size)
{
    const float* x  = (const float*)d_in[0];
    const float* Wq = (const float*)d_in[1];
    const float* Wk = (const float*)d_in[2];
    const float* Wv = (const float*)d_in[3];

    const long NTD = (long)NT * D_E;
    const long NTT = (long)N_B * T_S * T_S;

    float* dout = (float*)d_out;
    float* out_ptr;
    float* att_ptr;
    if ((long)out_size >= NTD + NTT) {
        out_ptr = dout;
        att_ptr = dout + NTD;
    } else if ((long)out_size == NTT) {
        att_ptr = dout;
        void* fb = nullptr;
        cudaGetSymbolAddress(&fb, g_out_fallback);
        out_ptr = (float*)fb;
    } else {
        out_ptr = dout;
        att_ptr = dout;
    }

    cudaFuncSetAttribute(qkv_mma_kernel, cudaFuncAttributeMaxDynamicSharedMemorySize, 2 * BUFSZ);
    cudaFuncSetAttribute(scores_mma_kernel, cudaFuncAttributeMaxDynamicSharedMemorySize, 2 * BUFSZ + 8192);
    cudaFuncSetAttribute(pv_mma_kernel, cudaFuncAttributeMaxDynamicSharedMemorySize, 2 * BUFSZ + 16384);

    wt_kernel<<<dim3(DIN / 32, D_E / 32, 3), 256>>>(Wq, Wk, Wv);

    qkv_mma_kernel<<<dim3(3, NT / 128), 256, 2 * BUFSZ>>>(x);

    scores_mma_kernel<<<dim3(1024, N_B), 256, 2 * BUFSZ + 8192>>>(att_ptr);

    pv_mma_kernel<<<dim3(80, N_B), 256, 2 * BUFSZ + 16384>>>(att_ptr, out_ptr);

    reduce_kernel<<<dim3(96, N_B), 256>>>(out_ptr);
}

// round 17
// speedup vs baseline: 1.0752x; 1.0011x over previous
#include <cuda_runtime.h>
#include <cuda_bf16.h>
#include <math.h>
#include <stdint.h>

#define N_B 4
#define T_S 4096
#define DIN 1024
#define D_E 128
#define NT (N_B * T_S)
#define PCH 40      // smem row pitch in halfs (32 + 8 pad)
#define BUFSZ 40960 // one stage: 4 regions x 10240B

// ---- scratch (device globals: allocation-free) ----
__device__ __nv_bfloat16 g_wth[3 * D_E * DIN];
__device__ __nv_bfloat16 g_wtl[3 * D_E * DIN];
__device__ __nv_bfloat16 g_qh[NT * D_E];
__device__ __nv_bfloat16 g_ql[NT * D_E];
__device__ __nv_bfloat16 g_kh[NT * D_E];
__device__ __nv_bfloat16 g_kl[NT * D_E];
__device__ __nv_bfloat16 g_vth[(long)N_B * D_E * T_S];
__device__ __nv_bfloat16 g_vtl[(long)N_B * D_E * T_S];
__device__ float g_pmax[(long)NT * 32];
__device__ float g_psum[(long)NT * 32];
__device__ float g_out_fallback[NT * D_E];

__device__ __forceinline__ float neg_inf() { return __int_as_float(0xff800000); }

__device__ __forceinline__ uint32_t smem_u32(const void* p) {
    uint32_t a;
    asm("{ .reg .u64 t; cvta.to.shared.u64 t, %1; cvt.u32.u64 %0, t; }" : "=r"(a) : "l"(p));
    return a;
}
__device__ __forceinline__ void split_bf16(float x, __nv_bfloat16& h, __nv_bfloat16& l) {
    h = __float2bfloat16(x);
    l = __float2bfloat16(x - __bfloat162float(h));
}

#define CP16(dst, src) asm volatile("cp.async.cg.shared.global [%0], [%1], 16;" :: "r"(dst), "l"(src))
#define CPCOMMIT() asm volatile("cp.async.commit_group;" ::: "memory")
#define CPWAIT0() asm volatile("cp.async.wait_group 0;" ::: "memory")

__device__ __forceinline__ void ldsm_x4(uint32_t* r, uint32_t addr) {
    asm volatile("ldmatrix.sync.aligned.m8n8.x4.shared.b16 {%0,%1,%2,%3}, [%4];"
        : "=r"(r[0]), "=r"(r[1]), "=r"(r[2]), "=r"(r[3]) : "r"(addr));
}
__device__ __forceinline__ void mma_bf16(float* c, const uint32_t* a, const uint32_t* b) {
    asm volatile(
        "mma.sync.aligned.m16n8k16.row.col.f32.bf16.bf16.f32 "
        "{%0,%1,%2,%3}, {%4,%5,%6,%7}, {%8,%9}, {%0,%1,%2,%3};"
        : "+f"(c[0]), "+f"(c[1]), "+f"(c[2]), "+f"(c[3])
        : "r"(a[0]), "r"(a[1]), "r"(a[2]), "r"(a[3]), "r"(b[0]), "r"(b[1]));
}

// One k16 step, mt-serial. B frags loaded as nt-pair x4 (both k-halves).
// Region layout within a stage: Ah@0, Al@10240, Bh@20480, Bl@30720.
__device__ __forceinline__ void mma_tile_step2(uint32_t base, int ks,
                                               uint32_t aoff, uint32_t boff2,
                                               float (*acc)[4][4])
{
    uint32_t ko = (uint32_t)ks * 32;
    uint32_t bh[4][2], bl[4][2];
#pragma unroll
    for (int p = 0; p < 2; p++) {
        uint32_t r[4];
        uint32_t ro = boff2 + p * (16 * 80) + ko;
        ldsm_x4(r, base + 20480 + ro);
        bh[2 * p][0] = r[0]; bh[2 * p][1] = r[1];
        bh[2 * p + 1][0] = r[2]; bh[2 * p + 1][1] = r[3];
        ldsm_x4(r, base + 30720 + ro);
        bl[2 * p][0] = r[0]; bl[2 * p][1] = r[1];
        bl[2 * p + 1][0] = r[2]; bl[2 * p + 1][1] = r[3];
    }
#pragma unroll
    for (int mt = 0; mt < 4; mt++) {
        uint32_t ah[4], al[4];
        uint32_t ro = aoff + mt * (16 * 80) + ko;
        ldsm_x4(ah, base + ro);
        ldsm_x4(al, base + 10240 + ro);
#pragma unroll
        for (int nt = 0; nt < 4; nt++) {
            mma_bf16(acc[mt][nt], ah, bh[nt]);
            mma_bf16(acc[mt][nt], ah, bl[nt]);
            mma_bf16(acc[mt][nt], al, bh[nt]);
        }
    }
}

#define MK_AOFF(wm, lane) ((uint32_t)((wm) + ((lane) & 15)) * 80 + ((lane) >> 4) * 16)
#define MK_BOFF2(wn, lane) \
    ((uint32_t)((wn) + (((lane) >> 4) << 3) + ((lane) & 7)) * 80 + (((lane) >> 3) & 1) * 16)

// ============================================================
// K0: transpose + split W
// ============================================================
__global__ __launch_bounds__(256) void wt_kernel(const float* __restrict__ Wq,
                                                 const float* __restrict__ Wk,
                                                 const float* __restrict__ Wv)
{
    const float* W = (blockIdx.z == 0) ? Wq : ((blockIdx.z == 1) ? Wk : Wv);
    __shared__ float t[32][33];
    int tid = threadIdx.x;
    int tx = tid & 31, ty = tid >> 5;
    int k0 = blockIdx.x * 32, n0 = blockIdx.y * 32;
#pragma unroll
    for (int s = 0; s < 4; s++) t[ty + s * 8][tx] = W[(k0 + ty + s * 8) * D_E + n0 + tx];
    __syncthreads();
    long wb = (long)blockIdx.z * D_E * DIN;
#pragma unroll
    for (int s = 0; s < 4; s++) {
        int n = n0 + ty + s * 8, k = k0 + tx;
        __nv_bfloat16 h, l;
        split_bf16(t[tx][ty + s * 8], h, l);
        g_wth[wb + (long)n * DIN + k] = h;
        g_wtl[wb + (long)n * DIN + k] = l;
    }
}

// ============================================================
// K0b: zero the out buffer (pv accumulates via atomics for i>=8)
// ============================================================
__global__ __launch_bounds__(256) void zero_out_kernel(float* __restrict__ out)
{
    long idx = ((long)blockIdx.x * 256 + threadIdx.x) * 4;
    *(float4*)&out[idx] = make_float4(0.f, 0.f, 0.f, 0.f);
}

// ============================================================
// K1: QKV. A = x fp32 via LDG + on-the-fly bf16 split.
// W via cp.async. grid (3, NT/128); 2 CTAs/SM.
// ============================================================
__global__ __launch_bounds__(256, 2) void qkv_mma_kernel(const float* __restrict__ x)
{
    extern __shared__ char smc[];
    uint32_t sb = smem_u32(smc);
    int tid = threadIdx.x, lane = tid & 31, wid = tid >> 5;
    int w = blockIdx.x;
    long mBase = (long)blockIdx.y * 128;

    const float* xA = x + mBase * DIN;
    const __nv_bfloat16* sBh = g_wth + (long)w * D_E * DIN;
    const __nv_bfloat16* sBl = g_wtl + (long)w * D_E * DIN;

    int n = (int)(mBase >> 12);

    int wm = (wid >> 2) * 64, wn = (wid & 3) * 32;
    uint32_t aoff = MK_AOFF(wm, lane);
    uint32_t boff2 = MK_BOFF2(wn, lane);

    float acc[4][4][4];
#pragma unroll
    for (int a = 0; a < 4; a++)
#pragma unroll
        for (int b = 0; b < 4; b++)
#pragma unroll
            for (int cc = 0; cc < 4; cc++) acc[a][b][cc] = 0.f;

    int arow = tid >> 3, aseg = tid & 7;

#define QKV_LDW(c, bf)                                                         \
    {                                                                          \
        int k0_ = (c) * 32;                                                    \
        uint32_t db_ = sb + (bf) * BUFSZ + 20480;                              \
        for (int u = tid; u < 1024; u += 256) {                                \
            int arr = u >> 9, idx = u & 511, row = idx >> 2, seg = idx & 3;    \
            const __nv_bfloat16* s = (arr ? sBl : sBh);                        \
            CP16(db_ + arr * 10240 + row * 80 + seg * 16,                      \
                 s + (long)row * DIN + k0_ + seg * 8);                         \
        }                                                                      \
        CPCOMMIT();                                                            \
    }

#define QKV_LDA(c, ar)                                                         \
    {                                                                          \
        int k0_ = (c) * 32;                                                    \
        _Pragma("unroll") for (int q = 0; q < 4; q++) {                        \
            ar[q] = *(const float4*)&xA[(long)(arow + q * 32) * DIN + k0_ + aseg * 4]; \
        }                                                                      \
    }

#define QKV_STA(bf, ar)                                                        \
    {                                                                          \
        _Pragma("unroll") for (int q = 0; q < 4; q++) {                        \
            __nv_bfloat16 h0, h1, h2, h3, l0, l1, l2, l3;                      \
            split_bf16(ar[q].x, h0, l0); split_bf16(ar[q].y, h1, l1);          \
            split_bf16(ar[q].z, h2, l2); split_bf16(ar[q].w, h3, l3);          \
            __nv_bfloat162 ph0, ph1, pl0, pl1;                                 \
            ph0.x = h0; ph0.y = h1; ph1.x = h2; ph1.y = h3;                    \
            pl0.x = l0; pl0.y = l1; pl1.x = l2; pl1.y = l3;                    \
            uint32_t so = (uint32_t)(arow + q * 32) * 80 + aseg * 8;           \
            *(uint2*)(smc + (bf) * BUFSZ + so) =                               \
                make_uint2(*(uint32_t*)&ph0, *(uint32_t*)&ph1);                \
            *(uint2*)(smc + (bf) * BUFSZ + 10240 + so) =                       \
                make_uint2(*(uint32_t*)&pl0, *(uint32_t*)&pl1);                \
        }                                                                      \
    }

    float4 ar[4];
    QKV_LDA(0, ar);
    QKV_LDW(0, 0);
    QKV_STA(0, ar);

    for (int c = 0; c < 32; c++) {
        CPWAIT0();
        __syncthreads();
        if (c + 1 < 32) {
            QKV_LDA(c + 1, ar);
            QKV_LDW(c + 1, (c + 1) & 1);
        }
        uint32_t base = sb + (c & 1) * BUFSZ;
        mma_tile_step2(base, 0, aoff, boff2, acc);
        mma_tile_step2(base, 1, aoff, boff2, acc);
        if (c + 1 < 32) QKV_STA((c + 1) & 1, ar);
    }
#undef QKV_LDW
#undef QKV_LDA
#undef QKV_STA
    __syncthreads();

    if (w < 2) {
        __nv_bfloat16* dh = w ? g_kh : g_qh;
        __nv_bfloat16* dl = w ? g_kl : g_ql;
#pragma unroll
        for (int mt = 0; mt < 4; mt++)
#pragma unroll
            for (int nt = 0; nt < 4; nt++) {
                int cc = wn + nt * 8 + (lane & 3) * 2;
#pragma unroll
                for (int h = 0; h < 2; h++) {
                    int row = wm + mt * 16 + (lane >> 2) + h * 8;
                    float v0 = acc[mt][nt][h * 2], v1 = acc[mt][nt][h * 2 + 1];
                    __nv_bfloat16 h0, h1, l0, l1;
                    split_bf16(v0, h0, l0);
                    split_bf16(v1, h1, l1);
                    __nv_bfloat162 ph, pl;
                    ph.x = h0; ph.y = h1; pl.x = l0; pl.y = l1;
                    long o = (mBase + row) * D_E + cc;
                    *(__nv_bfloat162*)&dh[o] = ph;
                    *(__nv_bfloat162*)&dl[o] = pl;
                }
            }
    } else {
        float* stage = (float*)smc;
#pragma unroll
        for (int mt = 0; mt < 4; mt++)
#pragma unroll
            for (int nt = 0; nt < 4; nt++) {
                int cc = wn + nt * 8 + (lane & 3) * 2;
#pragma unroll
                for (int h = 0; h < 2; h++) {
                    int row = wm + mt * 16 + (lane >> 2) + h * 8;
                    stage[row * 129 + cc] = acc[mt][nt][h * 2];
                    stage[row * 129 + cc + 1] = acc[mt][nt][h * 2 + 1];
                }
            }
        __syncthreads();
        int tb = (int)(mBase & (T_S - 1));
        for (int u = tid; u < 8192; u += 256) {
            int d = u >> 6, tp = (u & 63) * 2;
            float v0 = stage[tp * 129 + d];
            float v1 = stage[(tp + 1) * 129 + d];
            __nv_bfloat16 h0, h1, l0, l1;
            split_bf16(v0, h0, l0);
            split_bf16(v1, h1, l1);
            __nv_bfloat162 ph, pl;
            ph.x = h0; ph.y = h1; pl.x = l0; pl.y = l1;
            long o = ((long)n * D_E + d) * T_S + tb + tp;
            *(__nv_bfloat162*)&g_vth[o] = ph;
            *(__nv_bfloat162*)&g_vtl[o] = pl;
        }
    }
}

// ============================================================
// K2: scores. j>i tiles zero-fill; j<=i: S=QK^T, att stores
// u = exp(logit - M_tile), staged in smem -> coalesced float4 writes.
// Full tile written (zeros above diagonal) so pv needs no masks.
// ============================================================
__global__ __launch_bounds__(256, 2) void scores_mma_kernel(float* __restrict__ att)
{
    int i = blockIdx.x >> 5;
    int j = blockIdx.x & 31;
    int n = blockIdx.y;
    float* attn = att + (long)n * T_S * T_S;

    int tid = threadIdx.x;

    if (j > i) {
        float4 z = make_float4(0.f, 0.f, 0.f, 0.f);
        float* tp = attn + (long)(i * 128) * T_S + j * 128;
#pragma unroll 4
        for (int u = tid; u < 4096; u += 256) {
            int row = u >> 5, c4 = u & 31;
            *(float4*)&tp[(long)row * T_S + c4 * 4] = z;
        }
        return;
    }

    extern __shared__ char smc[];
    uint32_t sb = smem_u32(smc);
    int lane = tid & 31, wid = tid >> 5;

    const __nv_bfloat16* sAh = g_qh + ((long)n * T_S + i * 128) * D_E;
    const __nv_bfloat16* sAl = g_ql + ((long)n * T_S + i * 128) * D_E;
    const __nv_bfloat16* sBh = g_kh + ((long)n * T_S + j * 128) * D_E;
    const __nv_bfloat16* sBl = g_kl + ((long)n * T_S + j * 128) * D_E;

    int wm = (wid >> 2) * 64, wn = (wid & 3) * 32;
    uint32_t aoff = MK_AOFF(wm, lane);
    uint32_t boff2 = MK_BOFF2(wn, lane);

    float acc[4][4][4];
#pragma unroll
    for (int a = 0; a < 4; a++)
#pragma unroll
        for (int b = 0; b < 4; b++)
#pragma unroll
            for (int cc = 0; cc < 4; cc++) acc[a][b][cc] = 0.f;

#define SC_LOAD(c, bf)                                                         \
    {                                                                          \
        int k0_ = (c) * 32;                                                    \
        uint32_t db_ = sb + (bf) * BUFSZ;                                      \
        for (int u = tid; u < 2048; u += 256) {                                \
            int arr = u >> 9, idx = u & 511, row = idx >> 2, seg = idx & 3;    \
            const __nv_bfloat16* s =                                           \
                (arr == 0) ? sAh : (arr == 1) ? sAl : (arr == 2) ? sBh : sBl;  \
            CP16(db_ + arr * 10240 + row * 80 + seg * 16,                      \
                 s + (long)row * D_E + k0_ + seg * 8);                         \
        }                                                                      \
        CPCOMMIT();                                                            \
    }

    SC_LOAD(0, 0);
    for (int c = 0; c < 4; c++) {
        CPWAIT0();
        __syncthreads();
        if (c + 1 < 4) SC_LOAD(c + 1, (c + 1) & 1);
        uint32_t base = sb + (c & 1) * BUFSZ;
        mma_tile_step2(base, 0, aoff, boff2, acc);
        mma_tile_step2(base, 1, aoff, boff2, acc);
    }
#undef SC_LOAD

    float* pm = (float*)(smc + 2 * BUFSZ);
    float* ps = pm + 512;
    float* sM = ps + 512;
    float* stage = (float*)smc;             // reuse ring buffers: [128][132]
    float NI = neg_inf();

    __syncthreads();
    // phase 1: per-warp (32-col group) maxes
#pragma unroll
    for (int mt = 0; mt < 4; mt++)
#pragma unroll
        for (int h = 0; h < 2; h++) {
            int row = wm + mt * 16 + (lane >> 2) + h * 8;
            int tg = i * 128 + row;
            float m = NI;
#pragma unroll
            for (int nt = 0; nt < 4; nt++)
#pragma unroll
                for (int e = 0; e < 2; e++) {
                    int s = j * 128 + wn + nt * 8 + (lane & 3) * 2 + e;
                    if (s <= tg) {
                        float v = acc[mt][nt][h * 2 + e];
                        float ev = (v == 0.0f) ? NI : v;
                        m = fmaxf(m, ev);
                    }
                }
            m = fmaxf(m, __shfl_xor_sync(0xffffffffu, m, 1));
            m = fmaxf(m, __shfl_xor_sync(0xffffffffu, m, 2));
            if ((lane & 3) == 0) pm[row * 4 + (wid & 3)] = m;
        }
    __syncthreads();

    // phase 2: tile max per row
    if (tid < 128) {
        float m0 = pm[tid * 4], m1 = pm[tid * 4 + 1], m2 = pm[tid * 4 + 2], m3 = pm[tid * 4 + 3];
        sM[tid] = fmaxf(fmaxf(m0, m1), fmaxf(m2, m3));
    }
    __syncthreads();

    // phase 3: u = exp(v - M_tile) into stage smem + per-group sums
#pragma unroll
    for (int mt = 0; mt < 4; mt++)
#pragma unroll
        for (int h = 0; h < 2; h++) {
            int row = wm + mt * 16 + (lane >> 2) + h * 8;
            int tg = i * 128 + row;
            float M = sM[row];
            float ssum = 0.f;
#pragma unroll
            for (int nt = 0; nt < 4; nt++)
#pragma unroll
                for (int e = 0; e < 2; e++) {
                    int col = wn + nt * 8 + (lane & 3) * 2 + e;
                    int s = j * 128 + col;
                    float u = 0.f;
                    if (s <= tg && M != NI) {
                        float v = acc[mt][nt][h * 2 + e];
                        if (v != 0.0f) {
                            u = __expf(v - M);
                            ssum += u;
                        }
                    }
                    stage[row * 132 + col] = u;
                }
            ssum += __shfl_xor_sync(0xffffffffu, ssum, 1);
            ssum += __shfl_xor_sync(0xffffffffu, ssum, 2);
            if ((lane & 3) == 0) ps[row * 4 + (wid & 3)] = ssum;
        }
    __syncthreads();

    // coalesced tile write: 512B per warp-row
    {
        float* tp = attn + (long)(i * 128) * T_S + j * 128;
#pragma unroll 4
        for (int u = tid; u < 4096; u += 256) {
            int row = u >> 5, c4 = u & 31;
            *(float4*)&tp[(long)row * T_S + c4 * 4] = *(float4*)&stage[row * 132 + c4 * 4];
        }
    }

    if (tid < 128) {
        float S = ps[tid * 4] + ps[tid * 4 + 1] + ps[tid * 4 + 2] + ps[tid * 4 + 3];
        long o = ((long)n * T_S + i * 128 + tid) * 32 + j;
        g_pmax[o] = sM[tid];
        g_psum[o] = S;
    }
}

// ============================================================
// K4: split-K PV, K-group = 1024 cols. grid (80, N_B).
// att holds u (zeros above diagonal -> no masks needed).
// p = u * f; output via direct store (ngroups==1) or atomicAdd.
// ============================================================
__global__ __launch_bounds__(256, 2) void pv_mma_kernel(float* __restrict__ att,
                                                        float* __restrict__ out)
{
    int b = blockIdx.x;
    int n = blockIdx.y;
    int i = 31, jg = 0;
    for (i = 31; i >= 0; --i) {
        int g = (i + 8) >> 3;
        if (b < g) { jg = b; break; }
        b -= g;
    }
    int ngroups = (i + 8) >> 3;
    int kStart = jg << 10;
    int kEndA = min((jg + 1) << 10, (i + 1) << 7);
    int nc = (kEndA - kStart) >> 5;

    extern __shared__ char smc[];
    uint32_t sb = smem_u32(smc);
    float* sf = (float*)(smc + 2 * BUFSZ);  // [128][32] = 16KB
    int tid = threadIdx.x, lane = tid & 31, wid = tid >> 5;

    float* attn = att + (long)n * T_S * T_S;

    if (tid < 128) {
        long r = (long)n * T_S + (i << 7) + tid;
        const float* pmr = g_pmax + r * 32;
        const float* psr = g_psum + r * 32;
        float NI = neg_inf();
        float M = NI;
        for (int jj = 0; jj <= i; jj++) M = fmaxf(M, pmr[jj]);
        float S = 0.f;
        for (int jj = 0; jj <= i; jj++) {
            float mj = pmr[jj];
            if (mj != NI) S += psr[jj] * __expf(mj - M);
        }
        float inv = 1.f / S;
        for (int jj = 0; jj <= i; jj++) {
            float mj = pmr[jj];
            sf[tid * 32 + jj] = (mj != NI) ? __expf(mj - M) * inv : 0.f;
        }
    }
    __syncthreads();

    int wm = (wid >> 2) * 64, wn = (wid & 3) * 32;
    uint32_t aoff = MK_AOFF(wm, lane);
    uint32_t boff2 = MK_BOFF2(wn, lane);

    float acc[4][4][4];
#pragma unroll
    for (int a = 0; a < 4; a++)
#pragma unroll
        for (int b2 = 0; b2 < 4; b2++)
#pragma unroll
            for (int cc = 0; cc < 4; cc++) acc[a][b2][cc] = 0.f;

#define PV_LDB(c, bf)                                                          \
    {                                                                          \
        int k0_ = kStart + (c) * 32;                                           \
        uint32_t db_ = sb + (bf) * BUFSZ + 20480;                              \
        for (int u = tid; u < 1024; u += 256) {                                \
            int arr = u >> 9, idx = u & 511, row = idx >> 2, seg = idx & 3;    \
            const __nv_bfloat16* s = (arr ? g_vtl : g_vth) +                   \
                ((long)n * D_E + row) * T_S + k0_ + seg * 8;                   \
            CP16(db_ + arr * 10240 + row * 80 + seg * 16, s);                  \
        }                                                                      \
        CPCOMMIT();                                                            \
    }

#define PV_LDA(c, ar)                                                          \
    {                                                                          \
        int k0_ = kStart + (c) * 32;                                           \
        _Pragma("unroll") for (int q = 0; q < 4; q++) {                        \
            int idx = tid + q * 256;                                           \
            int row = idx >> 3, seg = idx & 7;                                 \
            ar[q] = *(const float4*)&attn[(long)((i << 7) + row) * T_S + k0_ + seg * 4]; \
        }                                                                      \
    }

#define PV_PROC(c, ar, bf)                                                     \
    {                                                                          \
        int k0_ = kStart + (c) * 32;                                           \
        int jt_ = k0_ >> 7;                                                    \
        _Pragma("unroll") for (int q = 0; q < 4; q++) {                        \
            int idx = tid + q * 256;                                           \
            int row = idx >> 3, seg = idx & 7;                                 \
            int t = (i << 7) + row;                                            \
            int s0 = k0_ + seg * 4;                                            \
            float f = sf[row * 32 + jt_];                                      \
            float p0 = ar[q].x * f;                                            \
            float p1 = ar[q].y * f;                                            \
            float p2 = ar[q].z * f;                                            \
            float p3 = ar[q].w * f;                                            \
            *(float4*)&attn[(long)t * T_S + s0] = make_float4(p0, p1, p2, p3); \
            __nv_bfloat16 h0, h1, h2, h3, l0, l1, l2, l3;                      \
            split_bf16(p0, h0, l0); split_bf16(p1, h1, l1);                    \
            split_bf16(p2, h2, l2); split_bf16(p3, h3, l3);                    \
            __nv_bfloat162 ph0, ph1, pl0, pl1;                                 \
            ph0.x = h0; ph0.y = h1; ph1.x = h2; ph1.y = h3;                    \
            pl0.x = l0; pl0.y = l1; pl1.x = l2; pl1.y = l3;                    \
            uint32_t so = row * 80 + seg * 8;                                  \
            *(uint2*)(smc + (bf) * BUFSZ + so) =                               \
                make_uint2(*(uint32_t*)&ph0, *(uint32_t*)&ph1);                \
            *(uint2*)(smc + (bf) * BUFSZ + 10240 + so) =                       \
                make_uint2(*(uint32_t*)&pl0, *(uint32_t*)&pl1);                \
        }                                                                      \
    }

    float4 ar[4];
    PV_LDB(0, 0);
    PV_LDA(0, ar);
    PV_PROC(0, ar, 0);

    for (int c = 0; c < nc; c++) {
        CPWAIT0();
        __syncthreads();
        if (c + 1 < nc) {
            PV_LDB(c + 1, (c + 1) & 1);
            PV_LDA(c + 1, ar);
        }
        uint32_t base = sb + (c & 1) * BUFSZ;
        mma_tile_step2(base, 0, aoff, boff2, acc);
        mma_tile_step2(base, 1, aoff, boff2, acc);
        if (c + 1 < nc) PV_PROC(c + 1, ar, (c + 1) & 1);
    }
#undef PV_LDB
#undef PV_LDA
#undef PV_PROC

    float* dst = out + ((long)n * T_S + (i << 7)) * D_E;
    if (ngroups == 1) {
#pragma unroll
        for (int mt = 0; mt < 4; mt++)
#pragma unroll
            for (int nt = 0; nt < 4; nt++) {
                int cc = wn + nt * 8 + (lane & 3) * 2;
#pragma unroll
                for (int h = 0; h < 2; h++) {
                    int row = wm + mt * 16 + (lane >> 2) + h * 8;
                    *(float2*)&dst[(long)row * 128 + cc] =
                        make_float2(acc[mt][nt][h * 2], acc[mt][nt][h * 2 + 1]);
                }
            }
    } else {
#pragma unroll
        for (int mt = 0; mt < 4; mt++)
#pragma unroll
            for (int nt = 0; nt < 4; nt++) {
                int cc = wn + nt * 8 + (lane & 3) * 2;
#pragma unroll
                for (int h = 0; h < 2; h++) {
                    int row = wm + mt * 16 + (lane >> 2) + h * 8;
                    atomicAdd(&dst[(long)row * 128 + cc], acc[mt][nt][h * 2]);
                    atomicAdd(&dst[(long)row * 128 + cc + 1], acc[mt][nt][h * 2 + 1]);
                }
            }
    }
}

// ============================================================
extern "C" void kernel_launch(void* const* d_in, const int* in_sizes, int n_in,
                              void* d_out, int out_size)
{
    const float* x  = (const float*)d_in[0];
    const float* Wq = (const float*)d_in[1];
    const float* Wk = (const float*)d_in[2];
    const float* Wv = (const float*)d_in[3];

    const long NTD = (long)NT * D_E;
    const long NTT = (long)N_B * T_S * T_S;

    float* dout = (float*)d_out;
    float* out_ptr;
    float* att_ptr;
    if ((long)out_size >= NTD + NTT) {
        out_ptr = dout;
        att_ptr = dout + NTD;
    } else if ((long)out_size == NTT) {
        att_ptr = dout;
        void* fb = nullptr;
        cudaGetSymbolAddress(&fb, g_out_fallback);
        out_ptr = (float*)fb;
    } else {
        out_ptr = dout;
        att_ptr = dout;
    }

    cudaFuncSetAttribute(qkv_mma_kernel, cudaFuncAttributeMaxDynamicSharedMemorySize, 2 * BUFSZ);
    cudaFuncSetAttribute(scores_mma_kernel, cudaFuncAttributeMaxDynamicSharedMemorySize, 2 * BUFSZ + 8192);
    cudaFuncSetAttribute(pv_mma_kernel, cudaFuncAttributeMaxDynamicSharedMemorySize, 2 * BUFSZ + 16384);

    wt_kernel<<<dim3(DIN / 32, D_E / 32, 3), 256>>>(Wq, Wk, Wv);

    zero_out_kernel<<<NTD / 1024, 256>>>(out_ptr);

    qkv_mma_kernel<<<dim3(3, NT / 128), 256, 2 * BUFSZ>>>(x);

    scores_mma_kernel<<<dim3(1024, N_B), 256, 2 * BUFSZ + 8192>>>(att_ptr);

    pv_mma_kernel<<<dim3(80, N_B), 256, 2 * BUFSZ + 16384>>>(att_ptr, out_ptr);
}